// round 9
// baseline (speedup 1.0000x reference)
#include <cuda_runtime.h>
#include <math.h>

#define B_    256
#define L_    8192
#define E_    64
#define THR_  1.5f

#define K1_BLOCKS 1024
#define K1_TH     256
#define K1_POS    8
#define CHUNK     2048

#define K2_TH     256

// scratch (device globals — allocation-free)
__device__ unsigned int g_cs[K1_BLOCKS * 1024];   // chunk-local cs, u16 pairs (4MB)
__device__ unsigned int g_psb[K1_BLOCKS * 64];    // ps bits, 1/position (256KB)
__device__ unsigned int g_tot[K1_BLOCKS];         // chunk token sums

// token byte r of the 5-word register window (r in 0..19, constant under unroll)
#define XB(r) ((w[(r) >> 2] >> (((r) & 3) * 8)) & 15u)

// ============================ kernel 1: entropy ============================
__global__ __launch_bounds__(K1_TH)
void k1(const int* __restrict__ x, float* __restrict__ out)
{
    __shared__ float tab[64];     // exact edge table (negated), (t-5)*10+c
    __shared__ int   wsum[8];

    const int bid  = blockIdx.x;
    const int tid  = threadIdx.x;
    const int lane = tid & 31;
    const int wid  = tid >> 5;
    const int row  = bid >> 2;
    const int rloc = (bid & 3) * CHUNK + tid * K1_POS;   // row-local base

    const int* xrow    = x + (size_t)row * L_;
    float*     out_ent = out + (size_t)B_ * E_ + (size_t)row * L_;

    if (tid < 50) {
        int c = tid % 10, t = tid / 10 + 5;
        float p = (float)c / (float)t;
        tab[tid] = -(p * log2f(p + 1e-12f));
    }

    // per-lane entropy tables in registers (lane = class count 0..9)
    float f1v, dDec, dInc;
    {
        float p = (float)lane / 9.0f;
        f1v = -(p * log2f(p + 1e-12f));
        float up = __shfl_up_sync(0xffffffffu, f1v, 1);
        float dn = __shfl_down_sync(0xffffffffu, f1v, 1);
        dDec = up - f1v;      // count c -> c-1 (queried with c>=1)
        dInc = dn - f1v;      // count c -> c+1 (queried with c<=8)
    }

    // register window: bytes rloc-4 .. rloc+15 (5 packed words, row-clamped)
    unsigned int w[5];
    {
        int w0 = (rloc >> 2) - 1;
        #pragma unroll
        for (int i = 0; i < 5; i++) {
            int wi = w0 + i;
            if (wi < 0) wi = 0;
            if (wi > (L_ / 4 - 1)) wi = L_ / 4 - 1;
            int4 a = ((const int4*)xrow)[wi];
            w[i] = (unsigned)a.x | ((unsigned)a.y << 8) |
                   ((unsigned)a.z << 16) | ((unsigned)a.w << 24);
        }
    }

    // block scan of token sums -> exclusive prefix r at rloc
    int lsum = 0;
    #pragma unroll
    for (int k = 0; k < K1_POS; k++) lsum += (int)XB(k + 4);
    int v = lsum;
    #pragma unroll
    for (int d = 1; d < 32; d <<= 1) {
        int u = __shfl_up_sync(0xffffffffu, v, d);
        if (lane >= d) v += u;
    }
    if (lane == 31) wsum[wid] = v;
    __syncthreads();
    int woff = 0;
    for (int ww = 0; ww < wid; ww++) woff += wsum[ww];
    int r = woff + v - lsum;

    // entropy via register-shuffle deltas; ps bits; cs pack — all registers
    unsigned int cnt = 0;
    #pragma unroll
    for (int q = 0; q < 9; q++) cnt += 1u << (XB(q) << 2);
    float S = 0.f;
    #pragma unroll
    for (int c = 0; c < 5; c++)
        S += __shfl_sync(0xffffffffu, f1v, (cnt >> (4 * c)) & 15);

    float ent[K1_POS];
    unsigned int csv[4];
    unsigned int mask = 0, cslo = 0;
    #pragma unroll
    for (int k = 0; k < K1_POS; k++) {
        if ((k & 1) == 0) cslo = (unsigned)r & 0xFFFFu;
        else              csv[k >> 1] = cslo | ((unsigned)r << 16);
        r += (int)XB(k + 4);
        ent[k] = S;
        mask |= (S > THR_) ? (1u << k) : 0u;
        int a = (int)XB(k);
        S += __shfl_sync(0xffffffffu, dDec, (cnt >> (4 * a)) & 15);
        cnt -= 1u << (4 * a);
        int b = (int)XB(k + 9);
        S += __shfl_sync(0xffffffffu, dInc, (cnt >> (4 * b)) & 15);
        cnt += 1u << (4 * b);
    }

    // row-edge fixup (t<9 windows): fully unrolled, constant bounds
    if (rloc == 0) {
        #pragma unroll
        for (int k = 0; k < 4; k++) {          // positions 0..3, window [0, k+4]
            unsigned int c = 0;
            #pragma unroll
            for (int rr = 4; rr <= 11; rr++)
                if (rr <= k + 8) c += 1u << (XB(rr) << 2);
            int t = k + 5;
            const float* tb = &tab[(t - 5) * 10];
            float e = tb[c & 15] + tb[(c >> 4) & 15] + tb[(c >> 8) & 15] +
                      tb[(c >> 12) & 15] + tb[(c >> 16) & 15];
            ent[k] = e;
            mask = (mask & ~(1u << k)) | ((e > THR_) ? (1u << k) : 0u);
        }
    }
    if (rloc == L_ - K1_POS) {
        #pragma unroll
        for (int k = 4; k < 8; k++) {          // positions 8188..8191, window [i-4, L-1]
            unsigned int c = 0;
            #pragma unroll
            for (int rr = 4; rr <= 11; rr++)
                if (rr >= k) c += 1u << (XB(rr) << 2);
            int t = 12 - k;
            const float* tb = &tab[(t - 5) * 10];
            float e = tb[c & 15] + tb[(c >> 4) & 15] + tb[(c >> 8) & 15] +
                      tb[(c >> 12) & 15] + tb[(c >> 16) & 15];
            ent[k] = e;
            mask = (mask & ~(1u << k)) | ((e > THR_) ? (1u << k) : 0u);
        }
    }

    // stores: entropy direct to gmem; cs + ps bits + chunk total to scratch
    {
        float4* eo = (float4*)(out_ent + rloc);
        eo[0] = make_float4(ent[0], ent[1], ent[2], ent[3]);
        eo[1] = make_float4(ent[4], ent[5], ent[6], ent[7]);
    }
    ((uint4*)&g_cs[bid * 1024])[tid] = make_uint4(csv[0], csv[1], csv[2], csv[3]);
    {
        unsigned int pv = mask << ((tid & 3) * 8);
        pv |= __shfl_xor_sync(0xffffffffu, pv, 1);
        pv |= __shfl_xor_sync(0xffffffffu, pv, 2);
        if ((tid & 3) == 0) g_psb[bid * 64 + (tid >> 2)] = pv;
    }
    if (tid == K1_TH - 1) g_tot[bid] = (unsigned)r;
}

// ====================== kernel 2: patching + tiny MLP ======================
__device__ __forceinline__ int cs_rd(const unsigned int* csw2, int i) {
    unsigned int v = csw2[i >> 1];
    return (i & 1) ? (int)(v >> 16) : (int)(v & 0xFFFFu);
}

__global__ __launch_bounds__(K2_TH)
void k2(const float* __restrict__ w1, const float* __restrict__ b1,
        const float* __restrict__ w2, const float* __restrict__ b2,
        float* __restrict__ out)
{
    __shared__ __align__(16) unsigned int csw2[4098];  // row cs (u16 pairs) + total
    __shared__ unsigned int  psb2[256];                // row ps bits
    __shared__ unsigned char exitt[64 * 12];
    __shared__ unsigned char gmap[8 * 12];
    __shared__ unsigned char gentry[8];
    __shared__ int   hist2[2][64];
    __shared__ int   hist[64];
    __shared__ float m_tab[64];
    __shared__ float hsall[E_];
    __shared__ float extra_m;
    __shared__ int   extra_c;

    const int row = blockIdx.x;
    const int tid = threadIdx.x;
    float* out_blt = out + (size_t)row * E_;

    if (tid < 62)
        m_tab[tid] = (tid < 13) ? ((float)tid / 3.0f) : ((float)(tid - 13) / 12.0f);
    if (tid < 128) hist2[tid >> 6][tid & 63] = 0;
    if (tid == 128) extra_c = 0;

    // chunk offsets (exact ints)
    unsigned int c0 = g_tot[row * 4 + 0], c1 = g_tot[row * 4 + 1];
    unsigned int c2 = g_tot[row * 4 + 2], c3 = g_tot[row * 4 + 3];

    // load cs with per-chunk offsets (u16 half-adds cannot carry: totals <= 32768)
    #pragma unroll
    for (int it = 0; it < 4; it++) {
        int vi = tid + it * K2_TH;              // uint4 index 0..1023
        int chunk = (vi * 4) >> 10;
        unsigned int off = (chunk == 0) ? 0u :
                           (chunk == 1) ? c0 :
                           (chunk == 2) ? (c0 + c1) : (c0 + c1 + c2);
        unsigned int oo = off * 0x00010001u;
        uint4 vv = ((const uint4*)&g_cs[row * 4096])[vi];
        vv.x += oo; vv.y += oo; vv.z += oo; vv.w += oo;
        ((uint4*)csw2)[vi] = vv;
    }
    if (tid == 64) csw2[4096] = (c0 + c1 + c2 + c3) & 0xFFFFu;
    psb2[tid] = g_psb[row * 256 + tid];
    __syncthreads();

    // phase 4: (seg, entry) exit offsets via register-bit walks (768 tasks)
    #pragma unroll
    for (int it = 0; it < 3; it++) {
        int task = tid + it * K2_TH;
        int sg = task / 12, e = task % 12;
        unsigned int a0 = psb2[4 * sg + 0], a1 = psb2[4 * sg + 1];
        unsigned int a2 = psb2[4 * sg + 2], a3 = psb2[4 * sg + 3];
        int p = e;
        while (p < 128) {
            unsigned int ws = (p < 64) ? ((p < 32) ? a0 : a1)
                                       : ((p < 96) ? a2 : a3);
            p += ((ws >> (p & 31)) & 1u) ? 3 : 12;
        }
        exitt[task] = (unsigned char)(p - 128);
    }
    __syncthreads();

    // phase 5a: compose 8-seg group maps
    if (tid < 96) {
        int g = tid / 12, e = tid % 12;
        int c = e;
        #pragma unroll
        for (int i = 0; i < 8; i++) c = exitt[(g * 8 + i) * 12 + c];
        gmap[g * 12 + e] = (unsigned char)c;
    }
    __syncthreads();

    // phase 5b: 8-link serial compose
    if (tid == 0) {
        int e = 0;
        #pragma unroll
        for (int g = 0; g < 8; g++) { gentry[g] = (unsigned char)e; e = gmap[g * 12 + e]; }
    }
    __syncthreads();

    // phase 6: 64 walkers, register ps bits, per-warp histograms
    if (tid < 64) {
        int g = tid >> 3;
        int c = gentry[g];
        for (int i = g * 8; i < tid; i++) c = exitt[i * 12 + c];
        unsigned int a0 = psb2[4 * tid + 0], a1 = psb2[4 * tid + 1];
        unsigned int a2 = psb2[4 * tid + 2], a3 = psb2[4 * tid + 3];
        int p = c, gb = tid * 128;
        int csnow = cs_rd(csw2, gb + p);
        int* myh = hist2[tid >> 5];
        while (p < 128) {
            unsigned int ws = (p < 64) ? ((p < 32) ? a0 : a1)
                                       : ((p < 96) ? a2 : a3);
            int bit = (ws >> (p & 31)) & 1;
            int psz = bit ? 3 : 12;
            int gj = gb + p + psz;
            if (gj > L_) {                       // truncated final patch
                int sum = cs_rd(csw2, L_) - csnow;
                extra_m = (float)sum / (float)(L_ - (gb + p));
                extra_c = 1;
                break;
            }
            int csj = cs_rd(csw2, gj);
            int bin = bit ? (csj - csnow) : (13 + csj - csnow);   // 0..61
            atomicAdd(&myh[bin], 1);
            csnow = csj;
            p += psz;
        }
    }
    __syncthreads();

    if (tid < 62) hist[tid] = hist2[0][tid] + hist2[1][tid];
    __syncthreads();

    // histogram -> hsall; final 64x64 matvec
    int n = 0;
    if (tid < E_) {
        float w1c = w1[tid], b1c = b1[tid];
        float hch = 0.f;
        #pragma unroll
        for (int b = 0; b < 62; b++) {
            int c = hist[b];
            hch += (float)c * fmaxf(fmaf(m_tab[b], w1c, b1c), 0.f);
            n += c;
        }
        if (extra_c) { hch += fmaxf(fmaf(extra_m, w1c, b1c), 0.f); n += 1; }
        hsall[tid] = hch;
    }
    __syncthreads();

    if (tid < E_) {
        const float* w2r = w2 + tid * E_;
        float acc = 0.f;
        #pragma unroll 8
        for (int j = 0; j < E_; j++) acc += hsall[j] * __ldg(&w2r[j]);
        out_blt[tid] = acc / (float)n + b2[tid];
    }
}

extern "C" void kernel_launch(void* const* d_in, const int* in_sizes, int n_in,
                              void* d_out, int out_size)
{
    const int*   x  = (const int*)d_in[0];
    const float* w1 = (const float*)d_in[1];
    const float* b1 = (const float*)d_in[2];
    const float* w2 = (const float*)d_in[3];
    const float* b2 = (const float*)d_in[4];
    float* out = (float*)d_out;
    k1<<<K1_BLOCKS, K1_TH>>>(x, out);
    k2<<<B_, K2_TH>>>(w1, b1, w2, b2, out);
}

// round 10
// speedup vs baseline: 1.3908x; 1.3908x over previous
#include <cuda_runtime.h>
#include <math.h>

#define B_    256
#define L_    8192
#define E_    64
#define THR_  1.5f
#define SEG_  64
#define NSEG_ 128          // L_/SEG_
#define NGRP_ 16           // NSEG_/8
#define NTH_  512
#define NWARP_ 16
#define PT_   16

struct Smem {
    unsigned short cs[L_ + 4];        // exact prefix sums (16KB)
    unsigned char  ps[L_];            // patch size per position (8KB)
    unsigned char  exitt[NSEG_ * 12]; // per-seg exit offsets
    unsigned char  gmap1[NGRP_ * 12]; // 8-seg group composed maps
    unsigned char  gentry[NGRP_];
    int            hist4[4][64];      // per-walker-warp histograms
    int            hist[64];
    float          m_tab[64];
    float          hsall[E_];
    float          tab[64];           // exact edge table (negated)
    int            wsum[NWARP_];
    float          extra_m;
    int            extra_c;
};

// token byte r of the 7-word register window (r in 0..27, constant under unroll)
#define XB(r) ((w[(r) >> 2] >> (((r) & 3) * 8)) & 15u)

__global__ __launch_bounds__(NTH_)
void ep_kernel(const int* __restrict__ x,
               const float* __restrict__ w1,
               const float* __restrict__ b1,
               const float* __restrict__ w2,
               const float* __restrict__ b2,
               float* __restrict__ out)
{
    extern __shared__ __align__(16) char dsm[];
    Smem* s = (Smem*)dsm;

    const int row  = blockIdx.x;
    const int tid  = threadIdx.x;
    const int lane = tid & 31;
    const int wid  = tid >> 5;

    const int* xrow    = x + (size_t)row * L_;
    float*     out_blt = out + (size_t)row * E_;
    float*     out_ent = out + (size_t)B_ * E_ + (size_t)row * L_;

    // ---- seed small tables; zero per-warp hists ----
    if (tid < 50) {                                  // exact edge table (negated)
        int c = tid % 10, t = tid / 10 + 5;
        float p = (float)c / (float)t;
        s->tab[tid] = -(p * log2f(p + 1e-12f));
    } else if (tid >= 64 && tid < 64 + 62) {
        int b = tid - 64;
        s->m_tab[b] = (b < 13) ? ((float)b / 3.0f) : ((float)(b - 13) / 12.0f);
    } else if (tid >= 128 && tid < 384) {
        ((int*)s->hist4)[tid - 128] = 0;
    } else if (tid == 384) {
        s->extra_c = 0;
    }

    // per-lane entropy table in registers (lane = class count 0..9)
    float f1v, dDec, dInc;
    {
        float p = (float)lane / 9.0f;
        f1v = -(p * log2f(p + 1e-12f));
        float up = __shfl_up_sync(0xffffffffu, f1v, 1);
        float dn = __shfl_down_sync(0xffffffffu, f1v, 1);
        dDec = up - f1v;      // count c -> c-1 (queried with c>=1)
        dInc = dn - f1v;      // count c -> c+1 (queried with c<=8)
    }

    // ---- register window: tokens base-4 .. base+23, straight from gmem ----
    const int base = tid * PT_;
    unsigned int w[7];
    {
        int w0 = (base >> 2) - 1;
        #pragma unroll
        for (int q = 0; q < 7; q++) {
            int wi = w0 + q;
            if (wi < 0) wi = 0;
            if (wi > (L_ / 4 - 1)) wi = L_ / 4 - 1;
            int4 a = ((const int4*)xrow)[wi];
            w[q] = (unsigned)a.x | ((unsigned)a.y << 8) |
                   ((unsigned)a.z << 16) | ((unsigned)a.w << 24);
        }
    }

    // ---- block scan -> exclusive prefix r at base ----
    int lsum = 0;
    #pragma unroll
    for (int k = 0; k < PT_; k++) lsum += (int)XB(k + 4);
    int v = lsum;
    #pragma unroll
    for (int d = 1; d < 32; d <<= 1) {
        int u = __shfl_up_sync(0xffffffffu, v, d);
        if (lane >= d) v += u;
    }
    if (lane == 31) s->wsum[wid] = v;
    __syncthreads();
    int woff = 0;
    for (int ww = 0; ww < wid; ww++) woff += s->wsum[ww];
    int r = woff + v - lsum;

    // ---- phase C: entropy (register deltas) + cs pack; ent kept in regs ----
    unsigned int cnt = 0;
    #pragma unroll
    for (int q = 0; q < 9; q++) cnt += 1u << (XB(q) << 2);
    float S = 0.f;
    #pragma unroll
    for (int c = 0; c < 5; c++)
        S += __shfl_sync(0xffffffffu, f1v, (cnt >> (4 * c)) & 15);

    float entv[PT_];
    unsigned int mask = 0, cslo = 0;
    unsigned int* csW = (unsigned int*)s->cs;
    #pragma unroll
    for (int k = 0; k < PT_; k++) {
        if ((k & 1) == 0) cslo = (unsigned)r & 0xFFFFu;
        else              csW[8 * tid + (k >> 1)] = cslo | ((unsigned)r << 16);
        r += (int)XB(k + 4);
        entv[k] = S;
        mask |= (S > THR_) ? (1u << k) : 0u;
        int a = (int)XB(k);
        S += __shfl_sync(0xffffffffu, dDec, (cnt >> (4 * a)) & 15);
        cnt -= 1u << (4 * a);
        int b = (int)XB(k + 9);
        S += __shfl_sync(0xffffffffu, dInc, (cnt >> (4 * b)) & 15);
        cnt += 1u << (4 * b);
    }
    if (tid == NTH_ - 1) s->cs[L_] = (unsigned short)r;

    // ---- row-edge fixups (t<9), in-register, exact table ----
    if (tid == 0) {
        #pragma unroll
        for (int k = 0; k < 4; k++) {       // positions 0..3, window [0, k+4]
            unsigned int c = 0;
            #pragma unroll
            for (int rr = 4; rr <= 12; rr++)
                if (rr <= k + 8) c += 1u << (XB(rr) << 2);
            int t = k + 5;
            const float* tb = &s->tab[(t - 5) * 10];
            float e = tb[c & 15] + tb[(c >> 4) & 15] + tb[(c >> 8) & 15] +
                      tb[(c >> 12) & 15] + tb[(c >> 16) & 15];
            entv[k] = e;
            mask = (mask & ~(1u << k)) | ((e > THR_) ? (1u << k) : 0u);
        }
    }
    if (tid == NTH_ - 1) {
        #pragma unroll
        for (int k = 12; k < 16; k++) {     // positions 8188..8191, window [i-4, L-1]
            unsigned int c = 0;
            #pragma unroll
            for (int rr = 12; rr <= 19; rr++)
                if (rr >= k) c += 1u << (XB(rr) << 2);
            int t = 20 - k;
            const float* tb = &s->tab[(t - 5) * 10];
            float e = tb[c & 15] + tb[(c >> 4) & 15] + tb[(c >> 8) & 15] +
                      tb[(c >> 12) & 15] + tb[(c >> 16) & 15];
            entv[k] = e;
            mask = (mask & ~(1u << k)) | ((e > THR_) ? (1u << k) : 0u);
        }
    }

    // ---- pack ps bytes; store entropy direct to gmem ----
    {
        unsigned int* psW = (unsigned int*)s->ps;
        #pragma unroll
        for (int q = 0; q < 4; q++) {
            unsigned int m4 = (mask >> (4 * q)) & 15u;
            unsigned int pw = 0x0C0C0C0Cu;              // all 12s
            pw ^= ((m4 & 1u) ? 0x0000000Fu : 0u);       // 12^15=3
            pw ^= ((m4 & 2u) ? 0x00000F00u : 0u);
            pw ^= ((m4 & 4u) ? 0x000F0000u : 0u);
            pw ^= ((m4 & 8u) ? 0x0F000000u : 0u);
            psW[4 * tid + q] = pw;
        }
        float4* eo = (float4*)(out_ent + base);
        eo[0] = make_float4(entv[0],  entv[1],  entv[2],  entv[3]);
        eo[1] = make_float4(entv[4],  entv[5],  entv[6],  entv[7]);
        eo[2] = make_float4(entv[8],  entv[9],  entv[10], entv[11]);
        eo[3] = make_float4(entv[12], entv[13], entv[14], entv[15]);
    }
    __syncthreads();

    // ---- phase 4: (seg, entry) exit offsets; 3 tasks/thread, interleaved ----
    {
        int t0 = tid, t1 = tid + NTH_, t2 = tid + 2 * NTH_;
        int p0 = (t0 / 12) * SEG_ + (t0 % 12), q0 = (t0 / 12) * SEG_ + SEG_;
        int p1 = (t1 / 12) * SEG_ + (t1 % 12), q1 = (t1 / 12) * SEG_ + SEG_;
        int p2 = (t2 / 12) * SEG_ + (t2 % 12), q2 = (t2 / 12) * SEG_ + SEG_;
        while (p0 < q0 || p1 < q1 || p2 < q2) {
            if (p0 < q0) p0 += s->ps[p0];
            if (p1 < q1) p1 += s->ps[p1];
            if (p2 < q2) p2 += s->ps[p2];
        }
        s->exitt[t0] = (unsigned char)(p0 - q0);
        s->exitt[t1] = (unsigned char)(p1 - q1);
        s->exitt[t2] = (unsigned char)(p2 - q2);
    }
    __syncthreads();

    // ---- compose: 16 groups of 8 segs x 12 entries ----
    if (tid < NGRP_ * 12) {
        int g = tid / 12, e = tid % 12;
        int c = e;
        #pragma unroll
        for (int i = 0; i < 8; i++) c = s->exitt[(g * 8 + i) * 12 + c];
        s->gmap1[tid] = (unsigned char)c;
    }
    __syncthreads();

    // ---- serial 16-link compose (thread 0) ----
    if (tid == 0) {
        int e = 0;
        #pragma unroll
        for (int g = 0; g < NGRP_; g++) {
            s->gentry[g] = (unsigned char)e;
            e = s->gmap1[g * 12 + e];
        }
    }
    __syncthreads();

    // ---- phase 6: 128 walkers (one 64-pos segment each) ----
    if (tid < NSEG_) {
        int g = tid >> 3;
        int c = s->gentry[g];
        for (int i = g * 8; i < tid; i++) c = s->exitt[i * 12 + c];
        int pos = tid * SEG_ + c;
        int end = tid * SEG_ + SEG_;
        int csprev = s->cs[pos];
        int* myh = s->hist4[tid >> 5];
        while (pos < end) {
            int psz = s->ps[pos];
            int j = pos + psz;
            if (j > L_) {                       // truncated final patch
                int sum = (int)s->cs[L_] - csprev;
                s->extra_m = (float)sum / (float)(L_ - pos);
                s->extra_c = 1;
                break;
            }
            int csj = s->cs[j];
            int bin = (psz == 3) ? (csj - csprev) : (13 + csj - csprev);  // 0..61
            atomicAdd(&myh[bin], 1);
            csprev = csj;
            pos = j;
        }
    }
    __syncthreads();

    // ---- reduce per-warp histograms ----
    if (tid < 62)
        s->hist[tid] = s->hist4[0][tid] + s->hist4[1][tid] +
                       s->hist4[2][tid] + s->hist4[3][tid];
    __syncthreads();

    // ---- histogram -> hsall; final 64x64 matvec ----
    int n = 0;
    if (tid < E_) {
        float w1c = w1[tid], b1c = b1[tid];
        float hch = 0.f;
        #pragma unroll
        for (int b = 0; b < 62; b++) {
            int c = s->hist[b];
            hch += (float)c * fmaxf(fmaf(s->m_tab[b], w1c, b1c), 0.f);
            n += c;
        }
        if (s->extra_c) { hch += fmaxf(fmaf(s->extra_m, w1c, b1c), 0.f); n += 1; }
        s->hsall[tid] = hch;
    }
    __syncthreads();

    if (tid < E_) {
        const float* w2r = w2 + tid * E_;
        float acc = 0.f;
        #pragma unroll 8
        for (int j = 0; j < E_; j++) acc += s->hsall[j] * __ldg(&w2r[j]);
        out_blt[tid] = acc / (float)n + b2[tid];
    }
}

extern "C" void kernel_launch(void* const* d_in, const int* in_sizes, int n_in,
                              void* d_out, int out_size)
{
    const int*   x  = (const int*)d_in[0];
    const float* w1 = (const float*)d_in[1];
    const float* b1 = (const float*)d_in[2];
    const float* w2 = (const float*)d_in[3];
    const float* b2 = (const float*)d_in[4];
    cudaFuncSetAttribute(ep_kernel, cudaFuncAttributeMaxDynamicSharedMemorySize,
                         (int)sizeof(Smem));
    ep_kernel<<<B_, NTH_, sizeof(Smem)>>>(x, w1, b1, w2, b2, (float*)d_out);
}